// round 6
// baseline (speedup 1.0000x reference)
#include <cuda_runtime.h>
#include <cstdint>

// Shapes: N=128, T=256, E=6, D=10
//   merged   : (128,256,14)  fp32  -- UNUSED
//   y_pred_i : (128,256,6)   fp32
//   y_pred_ij: (128,128,256,6) fp32  (dominant: ~100.7 MB, streamed once)
//   input1   : (128,256,15)  fp32  (err_true = cols 7..12)
//   samples  : (128,10)      fp32
//   labels   : (128,)        int64 -- UNUSED
// Output: scalar fp32 L_sim.

#define NPAIR 128
#define TE 1536              // T*E = 256*6
#define TE4 384              // TE/4

// second[i][j] stored twice (row-major + transposed) so the tail kernel
// reads both operands coalesced.
__device__ float g_second [NPAIR * NPAIR];
__device__ float g_secondT[NPAIR * NPAIR];

// ---------------------------------------------------------------------------
// Kernel 1: streaming kernel. R1-proven hot loop, now grid (j:128, grp:4)
// = 512 blocks (single wave at 4 blocks/SM) with each warp covering 4 rows
// via two sequential passes (unroll 1 keeps per-pass regs/MLP identical).
// second[i,j] = sum_{t,e} (yij[i,j,t,e] - yi[j,t,e])^2 / err[j,t,e]^2 / 15360
// ---------------------------------------------------------------------------
__global__ void __launch_bounds__(256)
second_kernel(const float* __restrict__ yij,
              const float* __restrict__ yi,
              const float* __restrict__ in1,
              float* __restrict__ out)
{
    __shared__ float4 w_s[TE4];
    __shared__ float4 y_s[TE4];

    const int j   = blockIdx.x;
    const int grp = blockIdx.y;
    const int tid = threadIdx.x;

    // Stage w[j,t,e] = (1/15360)/err^2 and y_pred_i[j] in smem.
    const float scale = 1.0f / 15360.0f;   // 1/(T*E*10)
    float*  w_f = reinterpret_cast<float*>(w_s);
    float*  y_f = reinterpret_cast<float*>(y_s);
    #pragma unroll
    for (int idx = tid; idx < TE; idx += 256) {
        int t = idx / 6;
        int c = idx - t * 6;
        float e = in1[(j * 256 + t) * 15 + 7 + c];
        w_f[idx] = scale / (e * e);
        y_f[idx] = yi[j * TE + idx];
    }

    // Zero the scalar output (tail kernel accumulates via atomicAdd).
    if (j == 0 && grp == 0 && tid == 0) out[0] = 0.0f;

    __syncthreads();

    const int warp = tid >> 5;
    const int lane = tid & 31;
    const int ibase = grp * 32 + warp * 4;   // 4 rows per warp

    #pragma unroll 1
    for (int pass = 0; pass < 2; ++pass) {
        const int i0 = ibase + pass * 2;

        const float4* p0 = reinterpret_cast<const float4*>(
            yij + (size_t)(i0 * NPAIR + j) * TE);
        const float4* p1 = reinterpret_cast<const float4*>(
            yij + (size_t)((i0 + 1) * NPAIR + j) * TE);

        float a0 = 0.0f, a1 = 0.0f;
        #pragma unroll
        for (int k = 0; k < 12; ++k) {
            const int x = lane + 32 * k;
            const float4 wv = w_s[x];
            const float4 yv = y_s[x];
            const float4 g0 = p0[x];
            const float4 g1 = p1[x];
            float d;
            d = g0.x - yv.x; a0 = fmaf(d * d, wv.x, a0);
            d = g0.y - yv.y; a0 = fmaf(d * d, wv.y, a0);
            d = g0.z - yv.z; a0 = fmaf(d * d, wv.z, a0);
            d = g0.w - yv.w; a0 = fmaf(d * d, wv.w, a0);
            d = g1.x - yv.x; a1 = fmaf(d * d, wv.x, a1);
            d = g1.y - yv.y; a1 = fmaf(d * d, wv.y, a1);
            d = g1.z - yv.z; a1 = fmaf(d * d, wv.z, a1);
            d = g1.w - yv.w; a1 = fmaf(d * d, wv.w, a1);
        }

        #pragma unroll
        for (int o = 16; o; o >>= 1) {
            a0 += __shfl_xor_sync(0xFFFFFFFFu, a0, o);
            a1 += __shfl_xor_sync(0xFFFFFFFFu, a1, o);
        }
        if (lane == 0) {
            g_second [i0 * NPAIR + j]       = a0;
            g_second [(i0 + 1) * NPAIR + j] = a1;
            g_secondT[j * NPAIR + i0]       = a0;   // transposed copy
            g_secondT[j * NPAIR + i0 + 1]   = a1;
        }
    }
}

// ---------------------------------------------------------------------------
// Kernel 2 (tail): 64 blocks x 256 threads, EXACTLY one (i,jj) pair per
// thread -> single latency round. All global reads coalesced or broadcast.
// L_sim = mean_{i,j} | S_ij - 0.5*(second[i,j] + second[j,i]) |
// ---------------------------------------------------------------------------
__global__ void __launch_bounds__(256)
final_kernel(const float* __restrict__ samples,
             float* __restrict__ out)
{
    __shared__ float s_part[8];

    const int tid = threadIdx.x;
    const int jj  = tid & 127;
    const int i   = blockIdx.x * 2 + (tid >> 7);

    // S_ij = mean_d (samples[i,d] - samples[jj,d])^2
    // samples[i,*] is a broadcast across the 128-thread half;
    // samples[jj,*] spans 10 lines per load (L1/L2-hit). All independent.
    float S = 0.0f;
    #pragma unroll
    for (int d = 0; d < 10; ++d) {
        float df = __ldg(&samples[i * 10 + d]) - __ldg(&samples[jj * 10 + d]);
        S = fmaf(df, df, S);
    }

    float sA = g_second [i * NPAIR + jj];   // second[i, jj]  (coalesced)
    float sB = g_secondT[i * NPAIR + jj];   // second[jj, i]  (coalesced)
    float v  = fabsf(S * 0.1f - 0.5f * (sA + sB));

    #pragma unroll
    for (int o = 16; o; o >>= 1)
        v += __shfl_xor_sync(0xFFFFFFFFu, v, o);
    if ((tid & 31) == 0) s_part[tid >> 5] = v;
    __syncthreads();

    if (tid == 0) {
        float s = 0.0f;
        #pragma unroll
        for (int w = 0; w < 8; ++w) s += s_part[w];
        atomicAdd(out, s * (1.0f / 16384.0f));
    }
}

// ---------------------------------------------------------------------------
extern "C" void kernel_launch(void* const* d_in, const int* in_sizes, int n_in,
                              void* d_out, int out_size)
{
    (void)in_sizes; (void)n_in; (void)out_size;
    const float* yi      = (const float*)d_in[1];
    const float* yij     = (const float*)d_in[2];
    const float* in1     = (const float*)d_in[3];
    const float* samples = (const float*)d_in[4];
    float* out = (float*)d_out;

    dim3 grid1(NPAIR, 4);               // 512 blocks -> single wave
    second_kernel<<<grid1, 256>>>(yij, yi, in1, out);
    final_kernel<<<64, 256>>>(samples, out);
}

// round 7
// speedup vs baseline: 2.0136x; 2.0136x over previous
#include <cuda_runtime.h>
#include <cstdint>

// Shapes: N=128, T=256, E=6, D=10
//   merged   : (128,256,14)  fp32  -- UNUSED
//   y_pred_i : (128,256,6)   fp32
//   y_pred_ij: (128,128,256,6) fp32  (dominant: ~100.7 MB, streamed once)
//   input1   : (128,256,15)  fp32  (err_true = cols 7..12)
//   samples  : (128,10)      fp32
//   labels   : (128,)        int64 -- UNUSED
// Output: scalar fp32 L_sim.

#define NPAIR 128
#define TE 1536              // T*E = 256*6
#define TE4 384              // TE/4

// second[i][j] stored twice (row-major + transposed) so the tail kernel
// reads both operands coalesced.
__device__ float g_second [NPAIR * NPAIR];
__device__ float g_secondT[NPAIR * NPAIR];

// ---------------------------------------------------------------------------
// Kernel 1: VERBATIM R5 streaming kernel (measured ~17.5 us, 5.7 TB/s).
// second[i,j] = sum_{t,e} (yij[i,j,t,e] - yi[j,t,e])^2 / err[j,t,e]^2 / 15360
// grid = (j: 128, i_grp: 8), block = 256 threads (8 warps), 2 rows/warp.
// ---------------------------------------------------------------------------
__global__ void __launch_bounds__(256)
second_kernel(const float* __restrict__ yij,
              const float* __restrict__ yi,
              const float* __restrict__ in1,
              float* __restrict__ out)
{
    __shared__ float4 w_s[TE4];
    __shared__ float4 y_s[TE4];

    const int j   = blockIdx.x;
    const int grp = blockIdx.y;
    const int tid = threadIdx.x;

    // Build weight tile w[j,t,e] = (1/15360) / err^2, and stage y_pred_i[j].
    const float scale = 1.0f / 15360.0f;   // 1/(T*E*10)
    float*  w_f = reinterpret_cast<float*>(w_s);
    float*  y_f = reinterpret_cast<float*>(y_s);
    #pragma unroll
    for (int idx = tid; idx < TE; idx += 256) {
        int t = idx / 6;
        int c = idx - t * 6;
        float e = in1[(j * 256 + t) * 15 + 7 + c];
        w_f[idx] = scale / (e * e);
        y_f[idx] = yi[j * TE + idx];
    }

    // Zero the scalar output (kernel 2 accumulates into it via atomicAdd).
    if (j == 0 && grp == 0 && tid == 0) out[0] = 0.0f;

    __syncthreads();

    const int warp = tid >> 5;
    const int lane = tid & 31;
    const int i0   = grp * 16 + warp * 2;     // this warp's two i rows

    const float4* p0 = reinterpret_cast<const float4*>(
        yij + (size_t)(i0 * NPAIR + j) * TE);
    const float4* p1 = reinterpret_cast<const float4*>(
        yij + (size_t)((i0 + 1) * NPAIR + j) * TE);

    float a0 = 0.0f, a1 = 0.0f;
    #pragma unroll
    for (int k = 0; k < 12; ++k) {
        const int x = lane + 32 * k;
        const float4 wv = w_s[x];
        const float4 yv = y_s[x];
        const float4 g0 = p0[x];
        const float4 g1 = p1[x];
        float d;
        d = g0.x - yv.x; a0 = fmaf(d * d, wv.x, a0);
        d = g0.y - yv.y; a0 = fmaf(d * d, wv.y, a0);
        d = g0.z - yv.z; a0 = fmaf(d * d, wv.z, a0);
        d = g0.w - yv.w; a0 = fmaf(d * d, wv.w, a0);
        d = g1.x - yv.x; a1 = fmaf(d * d, wv.x, a1);
        d = g1.y - yv.y; a1 = fmaf(d * d, wv.y, a1);
        d = g1.z - yv.z; a1 = fmaf(d * d, wv.z, a1);
        d = g1.w - yv.w; a1 = fmaf(d * d, wv.w, a1);
    }

    #pragma unroll
    for (int o = 16; o; o >>= 1) {
        a0 += __shfl_xor_sync(0xFFFFFFFFu, a0, o);
        a1 += __shfl_xor_sync(0xFFFFFFFFu, a1, o);
    }
    if (lane == 0) {
        g_second [i0 * NPAIR + j]        = a0;
        g_second [(i0 + 1) * NPAIR + j]  = a1;
        g_secondT[j * NPAIR + i0]        = a0;   // transposed copy
        g_secondT[j * NPAIR + i0 + 1]    = a1;
    }
}

// ---------------------------------------------------------------------------
// Kernel 2: VERBATIM R6 tail kernel (measured 4.2 us).
// 64 blocks x 256 threads, exactly one (i,jj) pair per thread -> one
// latency round. All global reads coalesced or broadcast.
// L_sim = mean_{i,j} | S_ij - 0.5*(second[i,j] + second[j,i]) |
// ---------------------------------------------------------------------------
__global__ void __launch_bounds__(256)
final_kernel(const float* __restrict__ samples,
             float* __restrict__ out)
{
    __shared__ float s_part[8];

    const int tid = threadIdx.x;
    const int jj  = tid & 127;
    const int i   = blockIdx.x * 2 + (tid >> 7);

    // S_ij = mean_d (samples[i,d] - samples[jj,d])^2
    float S = 0.0f;
    #pragma unroll
    for (int d = 0; d < 10; ++d) {
        float df = __ldg(&samples[i * 10 + d]) - __ldg(&samples[jj * 10 + d]);
        S = fmaf(df, df, S);
    }

    float sA = g_second [i * NPAIR + jj];   // second[i, jj]  (coalesced)
    float sB = g_secondT[i * NPAIR + jj];   // second[jj, i]  (coalesced)
    float v  = fabsf(S * 0.1f - 0.5f * (sA + sB));

    #pragma unroll
    for (int o = 16; o; o >>= 1)
        v += __shfl_xor_sync(0xFFFFFFFFu, v, o);
    if ((tid & 31) == 0) s_part[tid >> 5] = v;
    __syncthreads();

    if (tid == 0) {
        float s = 0.0f;
        #pragma unroll
        for (int w = 0; w < 8; ++w) s += s_part[w];
        atomicAdd(out, s * (1.0f / 16384.0f));
    }
}

// ---------------------------------------------------------------------------
extern "C" void kernel_launch(void* const* d_in, const int* in_sizes, int n_in,
                              void* d_out, int out_size)
{
    (void)in_sizes; (void)n_in; (void)out_size;
    const float* yi      = (const float*)d_in[1];
    const float* yij     = (const float*)d_in[2];
    const float* in1     = (const float*)d_in[3];
    const float* samples = (const float*)d_in[4];
    float* out = (float*)d_out;

    dim3 grid1(NPAIR, 8);
    second_kernel<<<grid1, 256>>>(yij, yi, in1, out);
    final_kernel<<<64, 256>>>(samples, out);
}

// round 8
// speedup vs baseline: 2.0611x; 1.0236x over previous
#include <cuda_runtime.h>
#include <cstdint>

// Shapes: N=128, T=256, E=6, D=10
//   merged   : (128,256,14)  fp32  -- UNUSED
//   y_pred_i : (128,256,6)   fp32
//   y_pred_ij: (128,128,256,6) fp32  (dominant: ~100.7 MB, streamed once)
//   input1   : (128,256,15)  fp32  (err_true = cols 7..12)
//   samples  : (128,10)      fp32
//   labels   : (128,)        int64 -- UNUSED
// Output: scalar fp32 L_sim.

#define NPAIR 128
#define TE 1536              // T*E = 256*6
#define TE4 384              // TE/4

// second[i][j] stored twice (row-major + transposed) so the tail kernel
// reads both operands coalesced.
__device__ float g_second [NPAIR * NPAIR];
__device__ float g_secondT[NPAIR * NPAIR];

// ---------------------------------------------------------------------------
// Kernel 1: R5/R7-proven streaming kernel (~19.1 us, 5.3 TB/s).
// Only change vs R7: a trailing cudaTriggerProgrammaticLaunchCompletion()
// (no-operand griddepcontrol; hot-loop codegen untouched).
// second[i,j] = sum_{t,e} (yij[i,j,t,e] - yi[j,t,e])^2 / err[j,t,e]^2 / 15360
// grid = (j: 128, i_grp: 8), block = 256 threads (8 warps), 2 rows/warp.
// ---------------------------------------------------------------------------
__global__ void __launch_bounds__(256)
second_kernel(const float* __restrict__ yij,
              const float* __restrict__ yi,
              const float* __restrict__ in1,
              float* __restrict__ out)
{
    __shared__ float4 w_s[TE4];
    __shared__ float4 y_s[TE4];

    const int j   = blockIdx.x;
    const int grp = blockIdx.y;
    const int tid = threadIdx.x;

    // Build weight tile w[j,t,e] = (1/15360) / err^2, and stage y_pred_i[j].
    const float scale = 1.0f / 15360.0f;   // 1/(T*E*10)
    float*  w_f = reinterpret_cast<float*>(w_s);
    float*  y_f = reinterpret_cast<float*>(y_s);
    #pragma unroll
    for (int idx = tid; idx < TE; idx += 256) {
        int t = idx / 6;
        int c = idx - t * 6;
        float e = in1[(j * 256 + t) * 15 + 7 + c];
        w_f[idx] = scale / (e * e);
        y_f[idx] = yi[j * TE + idx];
    }

    // Zero the scalar output (tail kernel accumulates into it via atomicAdd;
    // ordered by the grid dependency).
    if (j == 0 && grp == 0 && tid == 0) out[0] = 0.0f;

    __syncthreads();

    const int warp = tid >> 5;
    const int lane = tid & 31;
    const int i0   = grp * 16 + warp * 2;     // this warp's two i rows

    const float4* p0 = reinterpret_cast<const float4*>(
        yij + (size_t)(i0 * NPAIR + j) * TE);
    const float4* p1 = reinterpret_cast<const float4*>(
        yij + (size_t)((i0 + 1) * NPAIR + j) * TE);

    float a0 = 0.0f, a1 = 0.0f;
    #pragma unroll
    for (int k = 0; k < 12; ++k) {
        const int x = lane + 32 * k;
        const float4 wv = w_s[x];
        const float4 yv = y_s[x];
        const float4 g0 = p0[x];
        const float4 g1 = p1[x];
        float d;
        d = g0.x - yv.x; a0 = fmaf(d * d, wv.x, a0);
        d = g0.y - yv.y; a0 = fmaf(d * d, wv.y, a0);
        d = g0.z - yv.z; a0 = fmaf(d * d, wv.z, a0);
        d = g0.w - yv.w; a0 = fmaf(d * d, wv.w, a0);
        d = g1.x - yv.x; a1 = fmaf(d * d, wv.x, a1);
        d = g1.y - yv.y; a1 = fmaf(d * d, wv.y, a1);
        d = g1.z - yv.z; a1 = fmaf(d * d, wv.z, a1);
        d = g1.w - yv.w; a1 = fmaf(d * d, wv.w, a1);
    }

    #pragma unroll
    for (int o = 16; o; o >>= 1) {
        a0 += __shfl_xor_sync(0xFFFFFFFFu, a0, o);
        a1 += __shfl_xor_sync(0xFFFFFFFFu, a1, o);
    }
    if (lane == 0) {
        g_second [i0 * NPAIR + j]        = a0;
        g_second [(i0 + 1) * NPAIR + j]  = a1;
        g_secondT[j * NPAIR + i0]        = a0;   // transposed copy
        g_secondT[j * NPAIR + i0 + 1]    = a1;
    }

    // Let the dependent (tail) grid start launching while this grid drains.
    cudaTriggerProgrammaticLaunchCompletion();
}

// ---------------------------------------------------------------------------
// Kernel 2: R6/R7-proven tail kernel, now PDL-overlapped.
// 64 blocks x 256 threads, one (i,jj) pair per thread.
// The samples-only part of S_ij runs BEFORE the grid dependency sync
// (samples is an input, never written by kernel 1), hiding that latency
// round under the streamer's drain. g_second/g_secondT reads + atomicAdd
// happen after cudaGridDependencySynchronize().
// ---------------------------------------------------------------------------
__global__ void __launch_bounds__(256)
final_kernel(const float* __restrict__ samples,
             float* __restrict__ out)
{
    __shared__ float s_part[8];

    const int tid = threadIdx.x;
    const int jj  = tid & 127;
    const int i   = blockIdx.x * 2 + (tid >> 7);

    // S_ij = mean_d (samples[i,d] - samples[jj,d])^2  -- independent of k1.
    float S = 0.0f;
    #pragma unroll
    for (int d = 0; d < 10; ++d) {
        float df = __ldg(&samples[i * 10 + d]) - __ldg(&samples[jj * 10 + d]);
        S = fmaf(df, df, S);
    }

    // Wait for the streaming grid to fully complete (memory flushed).
    cudaGridDependencySynchronize();

    float sA = g_second [i * NPAIR + jj];   // second[i, jj]  (coalesced)
    float sB = g_secondT[i * NPAIR + jj];   // second[jj, i]  (coalesced)
    float v  = fabsf(S * 0.1f - 0.5f * (sA + sB));

    #pragma unroll
    for (int o = 16; o; o >>= 1)
        v += __shfl_xor_sync(0xFFFFFFFFu, v, o);
    if ((tid & 31) == 0) s_part[tid >> 5] = v;
    __syncthreads();

    if (tid == 0) {
        float s = 0.0f;
        #pragma unroll
        for (int w = 0; w < 8; ++w) s += s_part[w];
        atomicAdd(out, s * (1.0f / 16384.0f));
    }
}

// ---------------------------------------------------------------------------
extern "C" void kernel_launch(void* const* d_in, const int* in_sizes, int n_in,
                              void* d_out, int out_size)
{
    (void)in_sizes; (void)n_in; (void)out_size;
    const float* yi      = (const float*)d_in[1];
    const float* yij     = (const float*)d_in[2];
    const float* in1     = (const float*)d_in[3];
    const float* samples = (const float*)d_in[4];
    float* out = (float*)d_out;

    dim3 grid1(NPAIR, 8);
    second_kernel<<<grid1, 256>>>(yij, yi, in1, out);

    // Tail kernel with programmatic dependent launch (overlaps its launch
    // latency + samples loads with the streamer's drain).
    cudaLaunchAttribute attrs[1];
    attrs[0].id = cudaLaunchAttributeProgrammaticStreamSerialization;
    attrs[0].val.programmaticStreamSerializationAllowed = 1;

    cudaLaunchConfig_t cfg = {};
    cfg.gridDim  = dim3(64, 1, 1);
    cfg.blockDim = dim3(256, 1, 1);
    cfg.dynamicSmemBytes = 0;
    cfg.stream   = 0;
    cfg.attrs    = attrs;
    cfg.numAttrs = 1;
    cudaLaunchKernelEx(&cfg, final_kernel, samples, out);
}

// round 9
// speedup vs baseline: 2.2588x; 1.0959x over previous
#include <cuda_runtime.h>
#include <cstdint>

// Shapes: N=128, T=256, E=6, D=10
//   y_pred_i : (128,256,6)   fp32
//   y_pred_ij: (128,128,256,6) fp32  (~100.7 MB, streamed once via cp.async.bulk)
//   input1   : (128,256,15)  fp32  (err_true = cols 7..12)
//   samples  : (128,10)      fp32
// Output: scalar fp32 L_sim.

#define NPAIR 128
#define TE 1536                 // T*E
#define ROW_BYTES 6144          // TE * 4
#define NBUF 16                 // ring depth (2 buffers per consumer warp)

// smem layout (bytes, dynamic):
#define SM_W    0                       // w tile      (6144)
#define SM_Y    6144                    // y_pred_i[j] (6144)
#define SM_BUF  12288                   // 16 row buffers (98304)
#define SM_MBAR (12288 + 98304)         // full[16] @ +0, empty[16] @ +128
#define SMEM_TOTAL (SM_MBAR + 256)      // 110848

__device__ float g_second [NPAIR * NPAIR];
__device__ float g_secondT[NPAIR * NPAIR];

// ---- minimal PTX wrappers ---------------------------------------------------
__device__ __forceinline__ uint32_t smem_u32(const void* p) {
    return (uint32_t)__cvta_generic_to_shared(p);
}
__device__ __forceinline__ void mbar_init(uint32_t a, uint32_t cnt) {
    asm volatile("mbarrier.init.shared.b64 [%0], %1;" :: "r"(a), "r"(cnt) : "memory");
}
__device__ __forceinline__ void mbar_expect_tx(uint32_t a, uint32_t bytes) {
    asm volatile("mbarrier.arrive.expect_tx.shared.b64 _, [%0], %1;"
                 :: "r"(a), "r"(bytes) : "memory");
}
__device__ __forceinline__ void mbar_arrive(uint32_t a) {
    asm volatile("mbarrier.arrive.shared.b64 _, [%0];" :: "r"(a) : "memory");
}
__device__ __forceinline__ void mbar_wait(uint32_t a, uint32_t parity) {
    asm volatile(
        "{\n\t.reg .pred P;\n\t"
        "W_%=:\n\t"
        "mbarrier.try_wait.parity.acquire.cta.shared::cta.b64 P, [%0], %1, 0x989680;\n\t"
        "@P bra D_%=;\n\t"
        "bra W_%=;\n\t"
        "D_%=:\n\t}"
        :: "r"(a), "r"(parity) : "memory");
}
__device__ __forceinline__ void bulk_copy_g2s(uint32_t dst, const void* src,
                                              uint32_t bytes, uint32_t mbar) {
    asm volatile(
        "cp.async.bulk.shared::cluster.global.mbarrier::complete_tx::bytes "
        "[%0], [%1], %2, [%3];"
        :: "r"(dst), "l"(src), "r"(bytes), "r"(mbar) : "memory");
}

// ---------------------------------------------------------------------------
// Streaming kernel (bulk-async pipelined).
// grid = (j:128, half:2) = 256 blocks (single wave @ 2 blocks/SM).
// block = 288 threads: warps 0-7 consume, warp 8 produces.
// Row r (0..63) -> i = half*64 + r; buffer b = r & 15; round k = r >> 4.
// Consumer warp w owns buffers 2w, 2w+1 and rows i0 = half*64 + k*16 + 2w (+1).
// ---------------------------------------------------------------------------
__global__ void __launch_bounds__(288)
second_kernel(const float* __restrict__ yij,
              const float* __restrict__ yi,
              const float* __restrict__ in1,
              float* __restrict__ out)
{
    extern __shared__ __align__(128) unsigned char smem[];
    float* w_f = reinterpret_cast<float*>(smem + SM_W);
    float* y_f = reinterpret_cast<float*>(smem + SM_Y);
    const uint32_t sbase      = smem_u32(smem);
    const uint32_t mbar_full  = sbase + SM_MBAR;         // + 8*b
    const uint32_t mbar_empty = sbase + SM_MBAR + 128;   // + 8*b

    const int j    = blockIdx.x;
    const int half = blockIdx.y;
    const int tid  = threadIdx.x;

    if (tid < NBUF) {
        mbar_init(mbar_full  + tid * 8, 1);
        mbar_init(mbar_empty + tid * 8, 1);
    }

    // Stage w[j,t,e] = (1/15360)/err^2 and y_pred_i[j].
    const float scale = 1.0f / 15360.0f;   // 1/(T*E*10)
    for (int idx = tid; idx < TE; idx += 288) {
        int t = idx / 6;
        int c = idx - t * 6;
        float e = in1[(j * 256 + t) * 15 + 7 + c];
        w_f[idx] = scale / (e * e);
        y_f[idx] = yi[j * TE + idx];
    }
    if (j == 0 && half == 0 && tid == 0) out[0] = 0.0f;
    __syncthreads();   // mbarriers + staging visible before pipeline starts

    const int warp = tid >> 5;
    const int lane = tid & 31;

    if (warp == 8) {
        // ---- producer: one elected lane issues 64 bulk copies ---------------
        if (lane == 0) {
            for (int r = 0; r < 64; ++r) {
                const int b = r & 15;
                const int k = r >> 4;
                if (k > 0) mbar_wait(mbar_empty + b * 8, (unsigned)((k - 1) & 1));
                mbar_expect_tx(mbar_full + b * 8, ROW_BYTES);
                const float* src =
                    yij + (size_t)((half * 64 + r) * NPAIR + j) * TE;
                bulk_copy_g2s(sbase + SM_BUF + b * ROW_BYTES, src,
                              ROW_BYTES, mbar_full + b * 8);
            }
        }
        return;
    }

    // ---- consumers: warp w owns buffers 2w, 2w+1 ----------------------------
    const int b0 = 2 * warp;
    const int b1 = 2 * warp + 1;
    const float4* w4   = reinterpret_cast<const float4*>(w_f);
    const float4* y4   = reinterpret_cast<const float4*>(y_f);
    const float4* buf0 = reinterpret_cast<const float4*>(smem + SM_BUF + b0 * ROW_BYTES);
    const float4* buf1 = reinterpret_cast<const float4*>(smem + SM_BUF + b1 * ROW_BYTES);

    for (int k = 0; k < 4; ++k) {
        mbar_wait(mbar_full + b0 * 8, (unsigned)(k & 1));
        mbar_wait(mbar_full + b1 * 8, (unsigned)(k & 1));

        float a0 = 0.0f, a1 = 0.0f;
        #pragma unroll
        for (int q = 0; q < 12; ++q) {
            const int x = lane + 32 * q;
            const float4 wv = w4[x];
            const float4 yv = y4[x];
            const float4 g0 = buf0[x];
            const float4 g1 = buf1[x];
            float d;
            d = g0.x - yv.x; a0 = fmaf(d * d, wv.x, a0);
            d = g0.y - yv.y; a0 = fmaf(d * d, wv.y, a0);
            d = g0.z - yv.z; a0 = fmaf(d * d, wv.z, a0);
            d = g0.w - yv.w; a0 = fmaf(d * d, wv.w, a0);
            d = g1.x - yv.x; a1 = fmaf(d * d, wv.x, a1);
            d = g1.y - yv.y; a1 = fmaf(d * d, wv.y, a1);
            d = g1.z - yv.z; a1 = fmaf(d * d, wv.z, a1);
            d = g1.w - yv.w; a1 = fmaf(d * d, wv.w, a1);
        }
        #pragma unroll
        for (int o = 16; o; o >>= 1) {
            a0 += __shfl_xor_sync(0xFFFFFFFFu, a0, o);
            a1 += __shfl_xor_sync(0xFFFFFFFFu, a1, o);
        }
        __syncwarp();          // all lanes done reading the buffers
        if (lane == 0) {
            const int i0 = half * 64 + k * 16 + 2 * warp;
            g_second [i0 * NPAIR + j]       = a0;
            g_second [(i0 + 1) * NPAIR + j] = a1;
            g_secondT[j * NPAIR + i0]       = a0;
            g_secondT[j * NPAIR + i0 + 1]   = a1;
            mbar_arrive(mbar_empty + b0 * 8);   // release buffers
            mbar_arrive(mbar_empty + b1 * 8);
        }
    }
}

// ---------------------------------------------------------------------------
// Tail kernel: verbatim R8 (one (i,jj) pair per thread, PDL-overlapped).
// ---------------------------------------------------------------------------
__global__ void __launch_bounds__(256)
final_kernel(const float* __restrict__ samples,
             float* __restrict__ out)
{
    __shared__ float s_part[8];

    const int tid = threadIdx.x;
    const int jj  = tid & 127;
    const int i   = blockIdx.x * 2 + (tid >> 7);

    float S = 0.0f;
    #pragma unroll
    for (int d = 0; d < 10; ++d) {
        float df = __ldg(&samples[i * 10 + d]) - __ldg(&samples[jj * 10 + d]);
        S = fmaf(df, df, S);
    }

    cudaGridDependencySynchronize();

    float sA = g_second [i * NPAIR + jj];
    float sB = g_secondT[i * NPAIR + jj];
    float v  = fabsf(S * 0.1f - 0.5f * (sA + sB));

    #pragma unroll
    for (int o = 16; o; o >>= 1)
        v += __shfl_xor_sync(0xFFFFFFFFu, v, o);
    if ((tid & 31) == 0) s_part[tid >> 5] = v;
    __syncthreads();

    if (tid == 0) {
        float s = 0.0f;
        #pragma unroll
        for (int w = 0; w < 8; ++w) s += s_part[w];
        atomicAdd(out, s * (1.0f / 16384.0f));
    }
}

// ---------------------------------------------------------------------------
extern "C" void kernel_launch(void* const* d_in, const int* in_sizes, int n_in,
                              void* d_out, int out_size)
{
    (void)in_sizes; (void)n_in; (void)out_size;
    const float* yi      = (const float*)d_in[1];
    const float* yij     = (const float*)d_in[2];
    const float* in1     = (const float*)d_in[3];
    const float* samples = (const float*)d_in[4];
    float* out = (float*)d_out;

    static int smem_set = 0;
    if (!smem_set) {
        cudaFuncSetAttribute(second_kernel,
                             cudaFuncAttributeMaxDynamicSharedMemorySize,
                             SMEM_TOTAL);
        smem_set = 1;
    }

    dim3 grid1(NPAIR, 2);   // 256 blocks -> single wave at 2 blocks/SM
    second_kernel<<<grid1, 288, SMEM_TOTAL>>>(yij, yi, in1, out);

    cudaLaunchAttribute attrs[1];
    attrs[0].id = cudaLaunchAttributeProgrammaticStreamSerialization;
    attrs[0].val.programmaticStreamSerializationAllowed = 1;

    cudaLaunchConfig_t cfg = {};
    cfg.gridDim  = dim3(64, 1, 1);
    cfg.blockDim = dim3(256, 1, 1);
    cfg.dynamicSmemBytes = 0;
    cfg.stream   = 0;
    cfg.attrs    = attrs;
    cfg.numAttrs = 1;
    cudaLaunchKernelEx(&cfg, final_kernel, samples, out);
}